// round 7
// baseline (speedup 1.0000x reference)
#include <cuda_runtime.h>
#include <cstdint>
#include <cstddef>

#define T_STEPS 14
#define BSZ     8192
#define EMBED   256
#define HIDDEN  512
#define VOCAB   193
#define SEQLEN  15
#define GW      1536          // 3*HIDDEN

#define PITCH   36            // smem row pitch (floats) -> conflict-free frags
#define ATILE   (128 * PITCH) // 4608 floats per 128x32 tile
#define BTILE_F (3 * 64 * PITCH) // 6912 floats: 3 slabs x 64 rows x 32

// ---------------- scratch (device globals, ~252 MB) ------------------------
__device__ int   g_is64;
__device__ int   g_tok[T_STEPS * BSZ];
__device__ float g_G  [(size_t)VOCAB * GW];                    // gi lookup table
__device__ float g_h0 [(size_t)BSZ * HIDDEN];                  // 16 MB
__device__ float g_hs [(size_t)T_STEPS * BSZ * HIDDEN];        // 235 MB

// ---------------- token dtype detect + normalize ---------------------------
// If text is int64 (little-endian), every odd 32-bit word is 0 (tokens<193).
// For int32 tokens, 2048 sampled words all-zero has prob (1/193)^2048 ~ 0.
__global__ void detect_dtype_kernel(const int* __restrict__ text_words) {
    __shared__ int nz;
    if (threadIdx.x == 0) nz = 0;
    __syncthreads();
    for (int i = threadIdx.x; i < 2048; i += blockDim.x)
        if (text_words[2 * i + 1] != 0) atomicOr(&nz, 1);
    __syncthreads();
    if (threadIdx.x == 0) g_is64 = nz ? 0 : 1;
}

__global__ void convert_tok_kernel(const void* __restrict__ text) {
    int i = blockIdx.x * blockDim.x + threadIdx.x;     // i = b*14 + t
    if (i >= T_STEPS * BSZ) return;
    int b = i / T_STEPS, t = i - b * T_STEPS;
    int src = b * SEQLEN + t;
    int v;
    if (g_is64) v = (int)((const long long*)text)[src];
    else        v = ((const int*)text)[src];
    g_tok[i] = v;
}

// ---------------- G table: G[v][n] = emb[v] . W_ih[n] + b_ih[n] (fp32) -----
__global__ void build_G_kernel(const float* __restrict__ emb,
                               const float* __restrict__ W_ih,
                               const float* __restrict__ b_ih) {
    int idx = blockIdx.x * blockDim.x + threadIdx.x;
    if (idx >= VOCAB * GW) return;
    int v = idx / GW, n = idx - v * GW;
    const float* er = emb  + (size_t)v * EMBED;
    const float* wr = W_ih + (size_t)n * EMBED;
    float s = b_ih[n];
#pragma unroll 8
    for (int k = 0; k < EMBED; k++) s += er[k] * wr[k];
    g_G[idx] = s;
}

// ---------------- tf32 helpers ---------------------------------------------
__device__ __forceinline__ uint32_t f2tf32(float f) {
    uint32_t r;
    asm("cvt.rna.tf32.f32 %0, %1;" : "=r"(r) : "f"(f));
    return r;
}
__device__ __forceinline__ void mma_tf32(float c[4], const uint32_t a[4],
                                         const uint32_t b[2]) {
    asm volatile(
        "mma.sync.aligned.m16n8k8.row.col.f32.tf32.tf32.f32 "
        "{%0,%1,%2,%3}, {%4,%5,%6,%7}, {%8,%9}, {%0,%1,%2,%3};"
        : "+f"(c[0]), "+f"(c[1]), "+f"(c[2]), "+f"(c[3])
        : "r"(a[0]), "r"(a[1]), "r"(a[2]), "r"(a[3]), "r"(b[0]), "r"(b[1]));
}
__device__ __forceinline__ void cpa16(uint32_t d, const void* s) {
    asm volatile("cp.async.cg.shared.global [%0], [%1], 16;" :: "r"(d), "l"(s));
}
__device__ __forceinline__ void cp_commit() {
    asm volatile("cp.async.commit_group;");
}
template <int N> __device__ __forceinline__ void cp_wait() {
    asm volatile("cp.async.wait_group %0;" :: "n"(N));
}

// ---------------- generic double-buffered tf32 NT GEMM ---------------------
// C[M,N] = A[M,K] @ B[N,K]^T (+bias). K%32==0, M%128==0.
// mode 0: C[m*ldc+n].  mode 1: preds remap m=t*BSZ+b -> out[(b*14+t)*VOCAB+n].
// dynamic smem: 4*ATILE floats = 73728 B.
__global__ __launch_bounds__(256, 2) void gemm_tf32_db(
    const float* __restrict__ A, const float* __restrict__ Bm,
    const float* __restrict__ bias, float* __restrict__ C,
    int M, int N, int K, int ldc, int mode)
{
    extern __shared__ float sm[];
    float* As = sm;                  // [2][ATILE]
    float* Bs = sm + 2 * ATILE;      // [2][ATILE]
    uint32_t as_u = (uint32_t)__cvta_generic_to_shared(As);
    uint32_t bs_u = (uint32_t)__cvta_generic_to_shared(Bs);

    const int tid = threadIdx.x, lane = tid & 31, warp = tid >> 5;
    const int g = lane >> 2, t4 = lane & 3;
    const int m0 = blockIdx.y * 128, n0 = blockIdx.x * 128;
    const int wm0 = (warp >> 2) * 64, wn0 = (warp & 3) * 32;

    float acc[4][4][4];
#pragma unroll
    for (int mf = 0; mf < 4; mf++)
#pragma unroll
        for (int nf = 0; nf < 4; nf++)
#pragma unroll
            for (int e = 0; e < 4; e++) acc[mf][nf][e] = 0.f;

    auto load_tiles = [&](int k0, int buf) {
#pragma unroll
        for (int it = 0; it < 4; it++) {
            int idx = tid + it * 256;          // 0..1023
            int r = idx >> 3, c4 = idx & 7;
            cpa16(as_u + (uint32_t)(buf * ATILE + r * PITCH + c4 * 4) * 4,
                  A + (size_t)(m0 + r) * K + k0 + c4 * 4);
            int gn = n0 + r;
            if (gn < N) {
                cpa16(bs_u + (uint32_t)(buf * ATILE + r * PITCH + c4 * 4) * 4,
                      Bm + (size_t)gn * K + k0 + c4 * 4);
            } else {
                float4 z = make_float4(0.f, 0.f, 0.f, 0.f);
                *reinterpret_cast<float4*>(&Bs[buf * ATILE + r * PITCH + c4 * 4]) = z;
            }
        }
    };

    load_tiles(0, 0);
    cp_commit();
    int buf = 0;
    for (int k0 = 0; k0 < K; k0 += 32) {
        if (k0 + 32 < K) { load_tiles(k0 + 32, buf ^ 1); cp_commit(); cp_wait<1>(); }
        else             { cp_wait<0>(); }
        __syncthreads();
        const float* Ab = As + buf * ATILE;
        const float* Bb = Bs + buf * ATILE;
#pragma unroll
        for (int ks = 0; ks < 4; ks++) {
            uint32_t afr[4][4];
#pragma unroll
            for (int mf = 0; mf < 4; mf++) {
                const float* p = Ab + (wm0 + mf * 16 + g) * PITCH + ks * 8 + t4;
                afr[mf][0] = f2tf32(p[0]);
                afr[mf][1] = f2tf32(p[8 * PITCH]);
                afr[mf][2] = f2tf32(p[4]);
                afr[mf][3] = f2tf32(p[8 * PITCH + 4]);
            }
            uint32_t bfr[4][2];
#pragma unroll
            for (int nf = 0; nf < 4; nf++) {
                const float* p = Bb + (wn0 + nf * 8 + g) * PITCH + ks * 8 + t4;
                bfr[nf][0] = f2tf32(p[0]);
                bfr[nf][1] = f2tf32(p[4]);
            }
#pragma unroll
            for (int mf = 0; mf < 4; mf++)
#pragma unroll
                for (int nf = 0; nf < 4; nf++)
                    mma_tf32(acc[mf][nf], afr[mf], bfr[nf]);
        }
        __syncthreads();
        buf ^= 1;
    }

    // ---- epilogue ----
#pragma unroll
    for (int mf = 0; mf < 4; mf++) {
#pragma unroll
        for (int nf = 0; nf < 4; nf++) {
            int nbase = n0 + wn0 + nf * 8 + t4 * 2;
            float bias0 = 0.f, bias1 = 0.f;
            if (bias) {
                if (nbase < N)     bias0 = bias[nbase];
                if (nbase + 1 < N) bias1 = bias[nbase + 1];
            }
#pragma unroll
            for (int e = 0; e < 4; e++) {
                int m = m0 + wm0 + mf * 16 + g + ((e >= 2) ? 8 : 0);
                int n = nbase + (e & 1);
                if (n >= N) continue;
                float v = acc[mf][nf][e] + ((e & 1) ? bias1 : bias0);
                if (mode == 0) {
                    C[(size_t)m * ldc + n] = v;
                } else {
                    int t = m >> 13, b = m & (BSZ - 1);
                    C[((size_t)b * T_STEPS + t) * VOCAB + n] = v;
                }
            }
        }
    }
}

// ---------------- fused GRU step: 3-slab gh GEMM + gates in-register -------
// Block tile: 128 m-rows x 64 hidden-cols, computing r/z/n slabs together.
// grid = (HIDDEN/64, BSZ/128) = (8, 64). dynamic smem = (2*ATILE+2*BTILE_F)*4
// = 92160 B. Epilogue: h_t = (1-z)*tanh(Gn + r*ghn) + z*h_prev, gi from g_G.
__global__ __launch_bounds__(256, 1) void gru_fused_kernel(
    const float* __restrict__ W_hh, const float* __restrict__ b_hh, int t)
{
    extern __shared__ float sm[];
    float* As = sm;                   // [2][ATILE]
    float* Bs = sm + 2 * ATILE;       // [2][BTILE_F]
    uint32_t as_u = (uint32_t)__cvta_generic_to_shared(As);
    uint32_t bs_u = (uint32_t)__cvta_generic_to_shared(Bs);

    const float* hp   = (t == 0) ? g_h0 : (g_hs + (size_t)(t - 1) * BSZ * HIDDEN);
    float*       hout = g_hs + (size_t)t * BSZ * HIDDEN;

    const int tid = threadIdx.x, lane = tid & 31, warp = tid >> 5;
    const int g = lane >> 2, t4 = lane & 3;
    const int m0 = blockIdx.y * 128, n0 = blockIdx.x * 64;
    const int wm0 = (warp >> 1) * 32, wn0 = (warp & 1) * 32;

    float acc[3][2][4][4];
#pragma unroll
    for (int s = 0; s < 3; s++)
#pragma unroll
        for (int mf = 0; mf < 2; mf++)
#pragma unroll
            for (int nf = 0; nf < 4; nf++)
#pragma unroll
                for (int e = 0; e < 4; e++) acc[s][mf][nf][e] = 0.f;

    auto load_tiles = [&](int k0, int buf) {
#pragma unroll
        for (int it = 0; it < 4; it++) {       // A: 128 rows x 8 chunks
            int idx = tid + it * 256;
            int r = idx >> 3, c4 = idx & 7;
            cpa16(as_u + (uint32_t)(buf * ATILE + r * PITCH + c4 * 4) * 4,
                  hp + (size_t)(m0 + r) * HIDDEN + k0 + c4 * 4);
        }
#pragma unroll
        for (int it = 0; it < 6; it++) {       // B: 3 slabs x 64 rows x 8 chunks
            int idx = tid + it * 256;          // 0..1535
            int s  = idx >> 9;
            int rr = (idx >> 3) & 63;
            int c4 = idx & 7;
            cpa16(bs_u + (uint32_t)(buf * BTILE_F + (s * 64 + rr) * PITCH + c4 * 4) * 4,
                  W_hh + (size_t)(s * HIDDEN + n0 + rr) * HIDDEN + k0 + c4 * 4);
        }
    };

    load_tiles(0, 0);
    cp_commit();
    int buf = 0;
    for (int k0 = 0; k0 < HIDDEN; k0 += 32) {
        if (k0 + 32 < HIDDEN) { load_tiles(k0 + 32, buf ^ 1); cp_commit(); cp_wait<1>(); }
        else                  { cp_wait<0>(); }
        __syncthreads();
        const float* Ab = As + buf * ATILE;
        const float* Bb = Bs + buf * BTILE_F;
#pragma unroll
        for (int ks = 0; ks < 4; ks++) {
            uint32_t afr[2][4];
#pragma unroll
            for (int mf = 0; mf < 2; mf++) {
                const float* p = Ab + (wm0 + mf * 16 + g) * PITCH + ks * 8 + t4;
                afr[mf][0] = f2tf32(p[0]);
                afr[mf][1] = f2tf32(p[8 * PITCH]);
                afr[mf][2] = f2tf32(p[4]);
                afr[mf][3] = f2tf32(p[8 * PITCH + 4]);
            }
#pragma unroll
            for (int s = 0; s < 3; s++) {
                uint32_t bfr[4][2];
#pragma unroll
                for (int nf = 0; nf < 4; nf++) {
                    const float* p = Bb + (s * 64 + wn0 + nf * 8 + g) * PITCH + ks * 8 + t4;
                    bfr[nf][0] = f2tf32(p[0]);
                    bfr[nf][1] = f2tf32(p[4]);
                }
#pragma unroll
                for (int mf = 0; mf < 2; mf++)
#pragma unroll
                    for (int nf = 0; nf < 4; nf++)
                        mma_tf32(acc[s][mf][nf], afr[mf], bfr[nf]);
            }
        }
        __syncthreads();
        buf ^= 1;
    }

    // ---- fused GRU gate epilogue ----
#pragma unroll
    for (int mf = 0; mf < 2; mf++) {
#pragma unroll
        for (int eh = 0; eh < 2; eh++) {
            int m = m0 + wm0 + mf * 16 + g + eh * 8;
            int tok = g_tok[m * T_STEPS + t];
            const float* Gr   = g_G + (size_t)tok * GW;
            const float* hrow = hp   + (size_t)m * HIDDEN;
            float*       orow = hout + (size_t)m * HIDDEN;
#pragma unroll
            for (int nf = 0; nf < 4; nf++) {
#pragma unroll
                for (int el = 0; el < 2; el++) {
                    int hn = n0 + wn0 + nf * 8 + t4 * 2 + el;
                    int e = eh * 2 + el;
                    float gr  = acc[0][mf][nf][e] + b_hh[hn]              + Gr[hn];
                    float gz  = acc[1][mf][nf][e] + b_hh[HIDDEN + hn]     + Gr[HIDDEN + hn];
                    float ghn = acc[2][mf][nf][e] + b_hh[2 * HIDDEN + hn];
                    float r = 1.f / (1.f + expf(-gr));
                    float z = 1.f / (1.f + expf(-gz));
                    float nn = tanhf(Gr[2 * HIDDEN + hn] + r * ghn);
                    orow[hn] = (1.f - z) * nn + z * hrow[hn];
                }
            }
        }
    }
}

// ---------------- launch ----------------
extern "C" void kernel_launch(void* const* d_in, const int* in_sizes, int n_in,
                              void* d_out, int out_size)
{
    const float* img    = (const float*)d_in[0];
    const void*  text   = d_in[1];
    const float* emb    = (const float*)d_in[2];
    const float* W_proj = (const float*)d_in[3];
    const float* b_proj = (const float*)d_in[4];
    const float* W_ih   = (const float*)d_in[5];
    const float* W_hh   = (const float*)d_in[6];
    const float* b_ih   = (const float*)d_in[7];
    const float* b_hh   = (const float*)d_in[8];
    const float* W_out  = (const float*)d_in[9];
    const float* b_out  = (const float*)d_in[10];
    float* out = (float*)d_out;

    const int GEMM_SMEM = 4 * ATILE * 4;                       // 73728 B
    const int FUSE_SMEM = (2 * ATILE + 2 * BTILE_F) * 4;       // 92160 B
    cudaFuncSetAttribute(gemm_tf32_db,
        cudaFuncAttributeMaxDynamicSharedMemorySize, GEMM_SMEM);
    cudaFuncSetAttribute(gru_fused_kernel,
        cudaFuncAttributeMaxDynamicSharedMemorySize, FUSE_SMEM);

    float *ph0, *phs;
    cudaGetSymbolAddress((void**)&ph0, g_h0);
    cudaGetSymbolAddress((void**)&phs, g_hs);

    // 1) tokens
    detect_dtype_kernel<<<1, 256>>>((const int*)text);
    convert_tok_kernel<<<(T_STEPS * BSZ + 255) / 256, 256>>>(text);

    // 2) G lookup table (replaces the entire input-projection GEMM)
    build_G_kernel<<<(VOCAB * GW + 255) / 256, 256>>>(emb, W_ih, b_ih);

    // 3) h0 = img @ W_proj^T + b_proj   [8192, 512]
    gemm_tf32_db<<<dim3(HIDDEN / 128, BSZ / 128), 256, GEMM_SMEM>>>(
        img, W_proj, b_proj, ph0, BSZ, HIDDEN, 512, HIDDEN, 0);

    // 4) 14 fused GRU steps (gh GEMM for 3 slabs + gates, no intermediates)
    for (int t = 0; t < T_STEPS; t++)
        gru_fused_kernel<<<dim3(HIDDEN / 64, BSZ / 128), 256, FUSE_SMEM>>>(
            W_hh, b_hh, t);

    // 5) preds = hs @ W_out^T + b_out, remapped to [B, T, V]
    gemm_tf32_db<<<dim3(2, (T_STEPS * BSZ) / 128), 256, GEMM_SMEM>>>(
        phs, W_out, b_out, out, T_STEPS * BSZ, VOCAB, HIDDEN, VOCAB, 1);
}

// round 8
// speedup vs baseline: 1.2827x; 1.2827x over previous
#include <cuda_runtime.h>
#include <cstdint>
#include <cstddef>

#define T_STEPS 14
#define BSZ     8192
#define EMBED   256
#define HIDDEN  512
#define VOCAB   193
#define SEQLEN  15
#define GW      1536          // 3*HIDDEN

#define PITCH   36            // smem row pitch (uint32) -> conflict-free frags
#define ATILE   (128 * PITCH) // one 128x32 tile
#define NSTAGE  3
#define GEMM_SMEM (NSTAGE * 2 * ATILE * 4)   // 110592 B

// ---------------- scratch (device globals, ~560 MB) ------------------------
__device__ int   g_is64;
__device__ int   g_tok[T_STEPS * BSZ];
__device__ float g_G   [(size_t)VOCAB * GW];                   // gi lookup (fp32)
__device__ float g_gh  [(size_t)BSZ * GW];                     // 50 MB
__device__ float g_h0  [(size_t)BSZ * HIDDEN];                 // fp32 h0
__device__ float g_h032[(size_t)BSZ * HIDDEN];                 // tf32 h0
__device__ float g_hs  [(size_t)T_STEPS * BSZ * HIDDEN];       // fp32 states
__device__ float g_hs32[(size_t)T_STEPS * BSZ * HIDDEN];       // tf32 states
__device__ float g_img32 [(size_t)BSZ * 512];
__device__ float g_Wproj32[(size_t)HIDDEN * 512];
__device__ float g_Whh32 [(size_t)GW * HIDDEN];
__device__ float g_Wout32[(size_t)VOCAB * HIDDEN];

// ---------------- tf32 helpers ---------------------------------------------
__device__ __forceinline__ uint32_t f2tf32(float f) {
    uint32_t r;
    asm("cvt.rna.tf32.f32 %0, %1;" : "=r"(r) : "f"(f));
    return r;
}
__device__ __forceinline__ void mma_tf32(float c[4], const uint32_t a[4],
                                         const uint32_t b[2]) {
    asm volatile(
        "mma.sync.aligned.m16n8k8.row.col.f32.tf32.tf32.f32 "
        "{%0,%1,%2,%3}, {%4,%5,%6,%7}, {%8,%9}, {%0,%1,%2,%3};"
        : "+f"(c[0]), "+f"(c[1]), "+f"(c[2]), "+f"(c[3])
        : "r"(a[0]), "r"(a[1]), "r"(a[2]), "r"(a[3]), "r"(b[0]), "r"(b[1]));
}
__device__ __forceinline__ void cpa16(uint32_t d, const void* s) {
    asm volatile("cp.async.cg.shared.global [%0], [%1], 16;" :: "r"(d), "l"(s));
}
__device__ __forceinline__ void cp_commit() {
    asm volatile("cp.async.commit_group;");
}
template <int N> __device__ __forceinline__ void cp_wait() {
    asm volatile("cp.async.wait_group %0;" :: "n"(N));
}

// ---------------- token dtype detect + normalize ---------------------------
// int64 text (little-endian): every odd 32-bit word is 0 (tokens < 193).
__global__ void detect_dtype_kernel(const int* __restrict__ text_words) {
    __shared__ int nz;
    if (threadIdx.x == 0) nz = 0;
    __syncthreads();
    for (int i = threadIdx.x; i < 2048; i += blockDim.x)
        if (text_words[2 * i + 1] != 0) atomicOr(&nz, 1);
    __syncthreads();
    if (threadIdx.x == 0) g_is64 = nz ? 0 : 1;
}

__global__ void convert_tok_kernel(const void* __restrict__ text) {
    int i = blockIdx.x * blockDim.x + threadIdx.x;     // i = b*14 + t
    if (i >= T_STEPS * BSZ) return;
    int b = i / T_STEPS, t = i - b * T_STEPS;
    int src = b * SEQLEN + t;
    int v;
    if (g_is64) v = (int)((const long long*)text)[src];
    else        v = ((const int*)text)[src];
    g_tok[i] = v;
}

// ---------------- elementwise fp32 -> tf32 conversion ----------------------
__global__ void cvt_tf32_kernel(const float* __restrict__ src,
                                float* __restrict__ dst, int n) {
    int i = blockIdx.x * blockDim.x + threadIdx.x;
    if (i < n) dst[i] = __uint_as_float(f2tf32(src[i]));
}

// ---------------- G table: G[v][n] = emb[v].W_ih[n] + b_ih[n] (fp32) -------
__global__ void build_G_kernel(const float* __restrict__ emb,
                               const float* __restrict__ W_ih,
                               const float* __restrict__ b_ih) {
    int idx = blockIdx.x * blockDim.x + threadIdx.x;
    if (idx >= VOCAB * GW) return;
    int v = idx / GW, n = idx - v * GW;
    const float* er = emb  + (size_t)v * EMBED;
    const float* wr = W_ih + (size_t)n * EMBED;
    float s = b_ih[n];
#pragma unroll 8
    for (int k = 0; k < EMBED; k++) s += er[k] * wr[k];
    g_G[idx] = s;
}

// ---------------- 3-stage pipelined tf32 NT GEMM ---------------------------
// C[M,N] = A[M,K] @ B[N,K]^T + bias.  A,B already tf32. K%32==0, M%128==0.
// mode 0: C[m*ldc+n] (+ optional tf32 copy C32). mode 1: preds remap.
__global__ __launch_bounds__(256, 2) void gemm_tf32_p3(
    const float* __restrict__ A, const float* __restrict__ Bm,
    const float* __restrict__ bias, float* __restrict__ C,
    float* __restrict__ C32,
    int M, int N, int K, int ldc, int mode)
{
    extern __shared__ uint32_t sm[];
    uint32_t* As = sm;                       // [NSTAGE][ATILE]
    uint32_t* Bs = sm + NSTAGE * ATILE;      // [NSTAGE][ATILE]
    uint32_t as_u = (uint32_t)__cvta_generic_to_shared(As);
    uint32_t bs_u = (uint32_t)__cvta_generic_to_shared(Bs);

    const int tid = threadIdx.x, lane = tid & 31, warp = tid >> 5;
    const int g = lane >> 2, t4 = lane & 3;
    const int m0 = blockIdx.y * 128, n0 = blockIdx.x * 128;
    const int wm0 = (warp >> 2) * 64, wn0 = (warp & 3) * 32;

    float acc[4][4][4];
#pragma unroll
    for (int mf = 0; mf < 4; mf++)
#pragma unroll
        for (int nf = 0; nf < 4; nf++)
#pragma unroll
            for (int e = 0; e < 4; e++) acc[mf][nf][e] = 0.f;

    auto load_tiles = [&](int k0, int buf) {
#pragma unroll
        for (int it = 0; it < 4; it++) {
            int idx = tid + it * 256;          // 0..1023
            int r = idx >> 3, c4 = idx & 7;
            cpa16(as_u + (uint32_t)(buf * ATILE + r * PITCH + c4 * 4) * 4,
                  A + (size_t)(m0 + r) * K + k0 + c4 * 4);
            int gn = n0 + r;
            if (gn < N) {
                cpa16(bs_u + (uint32_t)(buf * ATILE + r * PITCH + c4 * 4) * 4,
                      Bm + (size_t)gn * K + k0 + c4 * 4);
            } else {
                uint4 z = make_uint4(0u, 0u, 0u, 0u);
                *reinterpret_cast<uint4*>(&Bs[buf * ATILE + r * PITCH + c4 * 4]) = z;
            }
        }
    };

    // prologue: stages 0,1 in flight
    load_tiles(0, 0);  cp_commit();
    if (32 < K) load_tiles(32, 1);
    cp_commit();

    int buf = 0;
    for (int k0 = 0; k0 < K; k0 += 32) {
        cp_wait<1>();        // tile for k0 retired (FIFO; 1 group may stay in flight)
        __syncthreads();     // cross-thread visibility + protects WAR on buffers
        const uint32_t* Ab = As + buf * ATILE;
        const uint32_t* Bb = Bs + buf * ATILE;
#pragma unroll
        for (int ks = 0; ks < 4; ks++) {
            uint32_t afr[4][4];
#pragma unroll
            for (int mf = 0; mf < 4; mf++) {
                const uint32_t* p = Ab + (wm0 + mf * 16 + g) * PITCH + ks * 8 + t4;
                afr[mf][0] = p[0];
                afr[mf][1] = p[8 * PITCH];
                afr[mf][2] = p[4];
                afr[mf][3] = p[8 * PITCH + 4];
            }
            uint32_t bfr[4][2];
#pragma unroll
            for (int nf = 0; nf < 4; nf++) {
                const uint32_t* p = Bb + (wn0 + nf * 8 + g) * PITCH + ks * 8 + t4;
                bfr[nf][0] = p[0];
                bfr[nf][1] = p[4];
            }
#pragma unroll
            for (int mf = 0; mf < 4; mf++)
#pragma unroll
                for (int nf = 0; nf < 4; nf++)
                    mma_tf32(acc[mf][nf], afr[mf], bfr[nf]);
        }
        // issue load for k0+64 into the buffer read last iteration (safe: the
        // __syncthreads above separated those reads from these writes)
        if (k0 + 64 < K) load_tiles(k0 + 64, (buf + 2) % NSTAGE);
        cp_commit();         // commit every iter (possibly empty) to keep FIFO math
        buf = (buf + 1) % NSTAGE;
    }

    // ---- epilogue ----
#pragma unroll
    for (int mf = 0; mf < 4; mf++) {
#pragma unroll
        for (int nf = 0; nf < 4; nf++) {
            int nbase = n0 + wn0 + nf * 8 + t4 * 2;
            float bias0 = 0.f, bias1 = 0.f;
            if (bias) {
                if (nbase < N)     bias0 = bias[nbase];
                if (nbase + 1 < N) bias1 = bias[nbase + 1];
            }
#pragma unroll
            for (int e = 0; e < 4; e++) {
                int m = m0 + wm0 + mf * 16 + g + ((e >= 2) ? 8 : 0);
                int n = nbase + (e & 1);
                if (n >= N) continue;
                float v = acc[mf][nf][e] + ((e & 1) ? bias1 : bias0);
                if (mode == 0) {
                    C[(size_t)m * ldc + n] = v;
                    if (C32) C32[(size_t)m * ldc + n] = __uint_as_float(f2tf32(v));
                } else {
                    int t = m >> 13, b = m & (BSZ - 1);
                    C[((size_t)b * T_STEPS + t) * VOCAB + n] = v;
                }
            }
        }
    }
}

// ---------------- gate kernel: h_t = GRU(G[tok], gh, h_prev), dual write ----
__global__ __launch_bounds__(256) void gate_kernel(int t)
{
    int idx = blockIdx.x * blockDim.x + threadIdx.x;   // one per 4 elems
    if (idx >= BSZ * (HIDDEN / 4)) return;
    int m = idx >> 7;            // HIDDEN/4 = 128
    int n = (idx & 127) * 4;

    const float* hp = (t == 0) ? g_h0 : (g_hs + (size_t)(t - 1) * BSZ * HIDDEN);
    float* hout   = g_hs   + (size_t)t * BSZ * HIDDEN;
    float* hout32 = g_hs32 + (size_t)t * BSZ * HIDDEN;
    int tok = g_tok[m * T_STEPS + t];

    const float* Gr = g_G  + (size_t)tok * GW;
    const float* gh = g_gh + (size_t)m * GW;

    float4 gir = *reinterpret_cast<const float4*>(&Gr[n]);
    float4 giz = *reinterpret_cast<const float4*>(&Gr[HIDDEN + n]);
    float4 gin = *reinterpret_cast<const float4*>(&Gr[2 * HIDDEN + n]);
    float4 ghr = *reinterpret_cast<const float4*>(&gh[n]);
    float4 ghz = *reinterpret_cast<const float4*>(&gh[HIDDEN + n]);
    float4 ghn = *reinterpret_cast<const float4*>(&gh[2 * HIDDEN + n]);
    float4 hv  = *reinterpret_cast<const float4*>(&hp[(size_t)m * HIDDEN + n]);

    float4 o;
    {
        float r = 1.f / (1.f + expf(-(gir.x + ghr.x)));
        float z = 1.f / (1.f + expf(-(giz.x + ghz.x)));
        float nn = tanhf(gin.x + r * ghn.x);
        o.x = (1.f - z) * nn + z * hv.x;
    }
    {
        float r = 1.f / (1.f + expf(-(gir.y + ghr.y)));
        float z = 1.f / (1.f + expf(-(giz.y + ghz.y)));
        float nn = tanhf(gin.y + r * ghn.y);
        o.y = (1.f - z) * nn + z * hv.y;
    }
    {
        float r = 1.f / (1.f + expf(-(gir.z + ghr.z)));
        float z = 1.f / (1.f + expf(-(giz.z + ghz.z)));
        float nn = tanhf(gin.z + r * ghn.z);
        o.z = (1.f - z) * nn + z * hv.z;
    }
    {
        float r = 1.f / (1.f + expf(-(gir.w + ghr.w)));
        float z = 1.f / (1.f + expf(-(giz.w + ghz.w)));
        float nn = tanhf(gin.w + r * ghn.w);
        o.w = (1.f - z) * nn + z * hv.w;
    }
    *reinterpret_cast<float4*>(&hout[(size_t)m * HIDDEN + n]) = o;
    float4 o32;
    o32.x = __uint_as_float(f2tf32(o.x));
    o32.y = __uint_as_float(f2tf32(o.y));
    o32.z = __uint_as_float(f2tf32(o.z));
    o32.w = __uint_as_float(f2tf32(o.w));
    *reinterpret_cast<float4*>(&hout32[(size_t)m * HIDDEN + n]) = o32;
}

// ---------------- launch ----------------
extern "C" void kernel_launch(void* const* d_in, const int* in_sizes, int n_in,
                              void* d_out, int out_size)
{
    const float* img    = (const float*)d_in[0];
    const void*  text   = d_in[1];
    const float* emb    = (const float*)d_in[2];
    const float* W_proj = (const float*)d_in[3];
    const float* b_proj = (const float*)d_in[4];
    const float* W_ih   = (const float*)d_in[5];
    const float* W_hh   = (const float*)d_in[6];
    const float* b_ih   = (const float*)d_in[7];
    const float* b_hh   = (const float*)d_in[8];
    const float* W_out  = (const float*)d_in[9];
    const float* b_out  = (const float*)d_in[10];
    float* out = (float*)d_out;

    cudaFuncSetAttribute(gemm_tf32_p3,
        cudaFuncAttributeMaxDynamicSharedMemorySize, GEMM_SMEM);

    float *ph0, *ph032, *phs, *phs32, *pgh;
    float *pimg32, *pWproj32, *pWhh32, *pWout32;
    cudaGetSymbolAddress((void**)&ph0,    g_h0);
    cudaGetSymbolAddress((void**)&ph032,  g_h032);
    cudaGetSymbolAddress((void**)&phs,    g_hs);
    cudaGetSymbolAddress((void**)&phs32,  g_hs32);
    cudaGetSymbolAddress((void**)&pgh,    g_gh);
    cudaGetSymbolAddress((void**)&pimg32, g_img32);
    cudaGetSymbolAddress((void**)&pWproj32, g_Wproj32);
    cudaGetSymbolAddress((void**)&pWhh32,   g_Whh32);
    cudaGetSymbolAddress((void**)&pWout32,  g_Wout32);

    // 1) tokens
    detect_dtype_kernel<<<1, 256>>>((const int*)text);
    convert_tok_kernel<<<(T_STEPS * BSZ + 255) / 256, 256>>>(text);

    // 2) pre-convert operands to tf32 (once)
    cvt_tf32_kernel<<<(BSZ * 512 + 255) / 256, 256>>>(img, pimg32, BSZ * 512);
    cvt_tf32_kernel<<<(HIDDEN * 512 + 255) / 256, 256>>>(W_proj, pWproj32, HIDDEN * 512);
    cvt_tf32_kernel<<<(GW * HIDDEN + 255) / 256, 256>>>(W_hh, pWhh32, GW * HIDDEN);
    cvt_tf32_kernel<<<(VOCAB * HIDDEN + 255) / 256, 256>>>(W_out, pWout32, VOCAB * HIDDEN);

    // 3) G lookup table (replaces the entire input-projection GEMM)
    build_G_kernel<<<(VOCAB * GW + 255) / 256, 256>>>(emb, W_ih, b_ih);

    // 4) h0 = img @ W_proj^T + b_proj  (writes fp32 + tf32 copies)
    gemm_tf32_p3<<<dim3(HIDDEN / 128, BSZ / 128), 256, GEMM_SMEM>>>(
        pimg32, pWproj32, b_proj, ph0, ph032, BSZ, HIDDEN, 512, HIDDEN, 0);

    // 5) 14 GRU steps: gh GEMM (pure tensor loop) + gate elementwise
    for (int t = 0; t < T_STEPS; t++) {
        const float* hp32 = (t == 0) ? ph032 : (phs32 + (size_t)(t - 1) * BSZ * HIDDEN);
        gemm_tf32_p3<<<dim3(GW / 128, BSZ / 128), 256, GEMM_SMEM>>>(
            hp32, pWhh32, b_hh, pgh, nullptr, BSZ, GW, HIDDEN, GW, 0);
        gate_kernel<<<(BSZ * (HIDDEN / 4) + 255) / 256, 256>>>(t);
    }

    // 6) preds = hs @ W_out^T + b_out, remapped to [B, T, V]
    gemm_tf32_p3<<<dim3(2, (T_STEPS * BSZ) / 128), 256, GEMM_SMEM>>>(
        phs32, pWout32, b_out, out, nullptr, T_STEPS * BSZ, VOCAB, HIDDEN, VOCAB, 1);
}